// round 12
// baseline (speedup 1.0000x reference)
#include <cuda_runtime.h>
#include <cstdint>
#include <cstddef>

#define BB 2
#define SS 1024
#define DD 1024
#define HH 16
#define LL 3
#define FF 4096
#define VV 32000
#define HDIM 64
#define MM (BB*SS)   // 2048 rows

// ---------------- static scratch (no allocations allowed) ----------------
__device__ float g_h[BB*SS*DD];        // residual stream
__device__ float g_ain[BB*SS*DD];      // layernorm output (fp32)
__device__ float g_q[BB*SS*DD];
__device__ float g_k[BB*SS*DD];
__device__ float g_v[BB*SS*DD];
__device__ float g_attn[BB*SS*DD];
__device__ float g_mid[BB*SS*FF];      // FFN hidden (fp32)
// tf32-rounded weights (converted once per call)
__device__ float g_wq[LL*DD*DD];
__device__ float g_wk[LL*DD*DD];
__device__ float g_wv[LL*DD*DD];
__device__ float g_wo[LL*DD*DD];
__device__ float g_w1[LL*DD*FF];
__device__ float g_w2[LL*FF*DD];
__device__ float g_wout[(size_t)DD*VV];

// ---------------- tf32 helpers ------------------------------------------
__device__ __forceinline__ uint32_t f2tf(float x) {
    uint32_t r;
    asm("cvt.rna.tf32.f32 %0, %1;" : "=r"(r) : "f"(x));
    return r;
}
__device__ __forceinline__ float tfround(float x) {
    return __uint_as_float(f2tf(x));
}
__device__ __forceinline__ void mma_tf32(float* c, const uint32_t* a, const uint32_t* b) {
    asm volatile(
        "mma.sync.aligned.m16n8k8.row.col.f32.tf32.tf32.f32 "
        "{%0,%1,%2,%3}, {%4,%5,%6,%7}, {%8,%9}, {%0,%1,%2,%3};"
        : "+f"(c[0]), "+f"(c[1]), "+f"(c[2]), "+f"(c[3])
        : "r"(a[0]), "r"(a[1]), "r"(a[2]), "r"(a[3]), "r"(b[0]), "r"(b[1]));
}
__device__ __forceinline__ void cp16(void* smem, const void* gmem) {
    uint32_t sa = (uint32_t)__cvta_generic_to_shared(smem);
    asm volatile("cp.async.cg.shared.global [%0], [%1], 16;\n" :: "r"(sa), "l"(gmem));
}
__device__ __forceinline__ void cp_commit() {
    asm volatile("cp.async.commit_group;\n" ::: "memory");
}
__device__ __forceinline__ void cp_wait_all() {
    asm volatile("cp.async.wait_group 0;\n" ::: "memory");
}

// ---------------- weight tf32 pre-conversion ----------------------------
__global__ void w_conv_kernel(const float4* __restrict__ src,
                              float4* __restrict__ dst, int n4) {
    int i = blockIdx.x * 256 + threadIdx.x;
    if (i < n4) {
        float4 v = src[i];
        v.x = tfround(v.x); v.y = tfround(v.y);
        v.z = tfround(v.z); v.w = tfround(v.w);
        dst[i] = v;
    }
}

// ---------------- embedding (token id dtype sniffed: int32 vs int64) ----
__global__ void embed_kernel(const void* __restrict__ x,
                             const float* __restrict__ tok,
                             const float* __restrict__ pos) {
    int row = blockIdx.x;          // b*SS + s
    int s = row % SS;
    const int* xi = (const int*)x;
    bool is64 = true;
    #pragma unroll
    for (int t = 0; t < 8; ++t) is64 = is64 && (xi[2*t+1] == 0);
    long long tokid = is64 ? ((const long long*)x)[row] : (long long)xi[row];
    const float* te = tok + (size_t)tokid * DD;
    const float* pe = pos + (size_t)s * DD;
    float* out = g_h + (size_t)row * DD;
    for (int c = threadIdx.x; c < DD; c += blockDim.x)
        out[c] = te[c] + pe[c];
}

// ---------------- layernorm: one block per row, 256 threads --------------
__global__ void ln_kernel(const float* __restrict__ in,
                          const float* __restrict__ g,
                          const float* __restrict__ b,
                          float* __restrict__ out) {
    int row = blockIdx.x;
    const float* xr = in + (size_t)row * DD;
    float s = 0.f, s2 = 0.f;
    for (int c = threadIdx.x; c < DD; c += 256) {
        float v = xr[c];
        s += v; s2 += v * v;
    }
    __shared__ float red[16];
    #pragma unroll
    for (int o = 16; o; o >>= 1) {
        s  += __shfl_down_sync(0xffffffffu, s,  o);
        s2 += __shfl_down_sync(0xffffffffu, s2, o);
    }
    int wid = threadIdx.x >> 5, lid = threadIdx.x & 31;
    if (lid == 0) { red[wid] = s; red[wid + 8] = s2; }
    __syncthreads();
    if (threadIdx.x == 0) {
        float ts = 0.f, ts2 = 0.f;
        #pragma unroll
        for (int w = 0; w < 8; ++w) { ts += red[w]; ts2 += red[w + 8]; }
        red[0] = ts; red[8] = ts2;
    }
    __syncthreads();
    float mu  = red[0] * (1.0f / DD);
    float var = red[8] * (1.0f / DD) - mu * mu;
    float inv = rsqrtf(var + 1e-5f);
    float* outr = out + (size_t)row * DD;
    for (int c = threadIdx.x; c < DD; c += 256)
        outr[c] = (xr[c] - mu) * inv * g[c] + b[c];
}

// ---------------- tf32 GEMM body: 128x128 tile, BK=16, 2-stage cp.async --
// A is fp32 (f2tf per fragment, exactly as the R6 passing kernel).
// B is pre-rounded tf32 (raw bits fed to mma; bit-identical to f2tf here).
// A smem [m][k] stride 20; B smem [k][n] stride 136 (both conflict-free).
__device__ __forceinline__
void gemm_body(const float* __restrict__ A, const float* __restrict__ Bm,
               const float* __restrict__ bias, const float* __restrict__ res,
               float* __restrict__ C, int N, int K, int do_gelu,
               float (*Asm)[128][20], float (*Bsm)[16][136]) {
    int tid = threadIdx.x;
    int lane = tid & 31, warp = tid >> 5;
    int wm = (warp >> 1) * 32;      // warp row offset in tile
    int wn = (warp & 1) * 64;       // warp col offset in tile
    int g  = lane >> 2, t4 = lane & 3;
    int row0 = blockIdx.y * 128, col0 = blockIdx.x * 128;

    float acc[2][8][4] = {};

    // staging descriptors
    int f0 = tid, f1 = tid + 256;
    int ar0 = f0 >> 2, ak0 = (f0 & 3) * 4;
    int ar1 = f1 >> 2, ak1 = (f1 & 3) * 4;
    int bk0 = f0 >> 5, bn0 = (f0 & 31) * 4;
    int bk1 = f1 >> 5, bn1 = (f1 & 31) * 4;

    #define STAGE(buf, kk) do { \
        cp16(&Asm[buf][ar0][ak0], A + (size_t)(row0 + ar0) * K + (kk) + ak0); \
        cp16(&Asm[buf][ar1][ak1], A + (size_t)(row0 + ar1) * K + (kk) + ak1); \
        cp16(&Bsm[buf][bk0][bn0], Bm + (size_t)((kk) + bk0) * N + col0 + bn0); \
        cp16(&Bsm[buf][bk1][bn1], Bm + (size_t)((kk) + bk1) * N + col0 + bn1); \
        cp_commit(); \
    } while (0)

    STAGE(0, 0);
    cp_wait_all();
    __syncthreads();

    int cur = 0;
    for (int kk = 0; kk < K; kk += 16) {
        bool has_next = (kk + 16) < K;
        if (has_next) STAGE(cur ^ 1, kk + 16);

        #pragma unroll
        for (int ks = 0; ks < 2; ++ks) {
            uint32_t af[2][4];
            #pragma unroll
            for (int mi = 0; mi < 2; ++mi) {
                int m = wm + mi * 16 + g;
                af[mi][0] = f2tf(Asm[cur][m    ][ks*8 + t4    ]);
                af[mi][1] = f2tf(Asm[cur][m + 8][ks*8 + t4    ]);
                af[mi][2] = f2tf(Asm[cur][m    ][ks*8 + t4 + 4]);
                af[mi][3] = f2tf(Asm[cur][m + 8][ks*8 + t4 + 4]);
            }
            #pragma unroll
            for (int ni = 0; ni < 8; ++ni) {
                int n = wn + ni * 8 + g;
                uint32_t bf[2];
                bf[0] = __float_as_uint(Bsm[cur][ks*8 + t4    ][n]);
                bf[1] = __float_as_uint(Bsm[cur][ks*8 + t4 + 4][n]);
                mma_tf32(acc[0][ni], af[0], bf);
                mma_tf32(acc[1][ni], af[1], bf);
            }
        }
        if (has_next) {
            cp_wait_all();
            __syncthreads();
            cur ^= 1;
        }
    }
    #undef STAGE

    // epilogue: bias (+ GELU) (+ residual), fp32 output
    #pragma unroll
    for (int mi = 0; mi < 2; ++mi) {
        #pragma unroll
        for (int ni = 0; ni < 8; ++ni) {
            int r = row0 + wm + mi * 16 + g;
            int c = col0 + wn + ni * 8 + 2 * t4;
            float bc0 = bias[c], bc1 = bias[c + 1];
            #pragma unroll
            for (int half = 0; half < 2; ++half) {
                int rr = r + half * 8;
                float v0 = acc[mi][ni][half * 2 + 0] + bc0;
                float v1 = acc[mi][ni][half * 2 + 1] + bc1;
                if (do_gelu) {
                    v0 = 0.5f * v0 * (1.0f + erff(v0 * 0.70710678118654752f));
                    v1 = 0.5f * v1 * (1.0f + erff(v1 * 0.70710678118654752f));
                }
                if (res) {
                    v0 += res[(size_t)rr * N + c];
                    v1 += res[(size_t)rr * N + c + 1];
                }
                *(float2*)(C + (size_t)rr * N + c) = make_float2(v0, v1);
            }
        }
    }
}

__global__ __launch_bounds__(256, 2)
void gemm_tf32(const float* __restrict__ A, const float* __restrict__ Bm,
               const float* __restrict__ bias, const float* __restrict__ res,
               float* __restrict__ C, int N, int K, int do_gelu) {
    __shared__ float Asm[2][128][20];
    __shared__ float Bsm[2][16][136];
    gemm_body(A, Bm, bias, res, C, N, K, do_gelu, Asm, Bsm);
}

// QKV fused: blockIdx.z selects weight/bias/output
__global__ __launch_bounds__(256, 2)
void gemm_qkv(const float* __restrict__ A,
              const float* __restrict__ W0, const float* __restrict__ W1_,
              const float* __restrict__ W2_,
              const float* __restrict__ b0, const float* __restrict__ b1_,
              const float* __restrict__ b2_,
              float* __restrict__ C0, float* __restrict__ C1,
              float* __restrict__ C2) {
    __shared__ float Asm[2][128][20];
    __shared__ float Bsm[2][16][136];
    const float* Bm; const float* bias; float* C;
    if (blockIdx.z == 0)      { Bm = W0;  bias = b0;  C = C0; }
    else if (blockIdx.z == 1) { Bm = W1_; bias = b1_; C = C1; }
    else                      { Bm = W2_; bias = b2_; C = C2; }
    gemm_body(A, Bm, bias, nullptr, C, DD, DD, 0, Asm, Bsm);
}

// ---------------- tf32 tensor-core flash attention (R6 version) ----------
// grid (SS/64, BB*HH), 128 threads (4 warps). q/k/v fp32; f2tf at staging.
#define QS_OFF 0
#define KS_OFF (64*68)
#define VS_OFF (KS_OFF + 64*68)
#define PS_OFF (VS_OFF + 64*72)
#define FLASH_SMEM ((PS_OFF + 64*72) * 4)

__global__ __launch_bounds__(128)
void flash_tc(const float* __restrict__ q, const float* __restrict__ kmat,
              const float* __restrict__ v, float* __restrict__ out) {
    extern __shared__ uint32_t fsm[];
    uint32_t (*Qs)[68] = (uint32_t(*)[68])(fsm + QS_OFF);
    uint32_t (*Ks)[68] = (uint32_t(*)[68])(fsm + KS_OFF);
    uint32_t (*Vs)[72] = (uint32_t(*)[72])(fsm + VS_OFF);
    uint32_t (*Ps)[72] = (uint32_t(*)[72])(fsm + PS_OFF);

    int bh = blockIdx.y;
    int b = bh >> 4, h = bh & 15;
    int rb = blockIdx.x * 64;
    const float* Q  = q    + (size_t)b * SS * DD + h * HDIM;
    const float* Kp = kmat + (size_t)b * SS * DD + h * HDIM;
    const float* V  = v    + (size_t)b * SS * DD + h * HDIM;

    int tid = threadIdx.x;
    int lane = tid & 31, warp = tid >> 5;
    int g = lane >> 2, t4 = lane & 3;
    int w16 = warp * 16;

    // stage Q (tf32): 64 rows x 64 d
    #pragma unroll
    for (int it = 0; it < 8; ++it) {
        int idx = it * 128 + tid;
        int row = idx >> 4, d4 = (idx & 15) * 4;
        float4 qv = *(const float4*)(Q + (size_t)(rb + row) * DD + d4);
        Qs[row][d4 + 0] = f2tf(qv.x); Qs[row][d4 + 1] = f2tf(qv.y);
        Qs[row][d4 + 2] = f2tf(qv.z); Qs[row][d4 + 3] = f2tf(qv.w);
    }

    float m_run[2] = {-1e30f, -1e30f};
    float l_run[2] = {0.f, 0.f};
    float accO[8][4] = {};

    int nblk = rb / 64 + 1;
    for (int blk = 0; blk < nblk; ++blk) {
        int j0 = blk * 64;
        __syncthreads();
        #pragma unroll
        for (int it = 0; it < 8; ++it) {
            int idx = it * 128 + tid;
            int row = idx >> 4, d4 = (idx & 15) * 4;
            float4 kv = *(const float4*)(Kp + (size_t)(j0 + row) * DD + d4);
            Ks[row][d4 + 0] = f2tf(kv.x); Ks[row][d4 + 1] = f2tf(kv.y);
            Ks[row][d4 + 2] = f2tf(kv.z); Ks[row][d4 + 3] = f2tf(kv.w);
            float4 vv = *(const float4*)(V + (size_t)(j0 + row) * DD + d4);
            Vs[row][d4 + 0] = f2tf(vv.x); Vs[row][d4 + 1] = f2tf(vv.y);
            Vs[row][d4 + 2] = f2tf(vv.z); Vs[row][d4 + 3] = f2tf(vv.w);
        }
        __syncthreads();

        // S = Q K^T
        float sacc[8][4] = {};
        #pragma unroll
        for (int kc = 0; kc < 8; ++kc) {
            uint32_t a[4];
            a[0] = Qs[w16 + g    ][kc*8 + t4    ];
            a[1] = Qs[w16 + g + 8][kc*8 + t4    ];
            a[2] = Qs[w16 + g    ][kc*8 + t4 + 4];
            a[3] = Qs[w16 + g + 8][kc*8 + t4 + 4];
            #pragma unroll
            for (int nt = 0; nt < 8; ++nt) {
                uint32_t bb[2];
                bb[0] = Ks[nt*8 + g][kc*8 + t4    ];
                bb[1] = Ks[nt*8 + g][kc*8 + t4 + 4];
                mma_tf32(sacc[nt], a, bb);
            }
        }

        // online softmax (fp32)
        #pragma unroll
        for (int hf = 0; hf < 2; ++hf) {
            int row = rb + w16 + g + hf * 8;
            float sv[8][2];
            float mloc = -1e30f;
            #pragma unroll
            for (int nt = 0; nt < 8; ++nt) {
                #pragma unroll
                for (int jj = 0; jj < 2; ++jj) {
                    float s = sacc[nt][hf*2 + jj] * 0.125f;
                    int col = j0 + nt*8 + 2*t4 + jj;
                    if (col > row) s = -1e30f;
                    sv[nt][jj] = s;
                    mloc = fmaxf(mloc, s);
                }
            }
            mloc = fmaxf(mloc, __shfl_xor_sync(0xffffffffu, mloc, 1));
            mloc = fmaxf(mloc, __shfl_xor_sync(0xffffffffu, mloc, 2));
            float mnew = fmaxf(m_run[hf], mloc);
            float sc = __expf(m_run[hf] - mnew);
            float ls = 0.f;
            #pragma unroll
            for (int nt = 0; nt < 8; ++nt) {
                #pragma unroll
                for (int jj = 0; jj < 2; ++jj) {
                    float p = __expf(sv[nt][jj] - mnew);
                    ls += p;
                    Ps[nt*8 + 2*t4 + jj][w16 + g + hf*8] = f2tf(p);
                }
            }
            ls += __shfl_xor_sync(0xffffffffu, ls, 1);
            ls += __shfl_xor_sync(0xffffffffu, ls, 2);
            l_run[hf] = l_run[hf] * sc + ls;
            m_run[hf] = mnew;
            #pragma unroll
            for (int nt = 0; nt < 8; ++nt) {
                accO[nt][hf*2 + 0] *= sc;
                accO[nt][hf*2 + 1] *= sc;
            }
        }
        __syncwarp();

        // O += P V
        #pragma unroll
        for (int kc = 0; kc < 8; ++kc) {
            uint32_t a[4];
            a[0] = Ps[kc*8 + t4    ][w16 + g    ];
            a[1] = Ps[kc*8 + t4    ][w16 + g + 8];
            a[2] = Ps[kc*8 + t4 + 4][w16 + g    ];
            a[3] = Ps[kc*8 + t4 + 4][w16 + g + 8];
            #pragma unroll
            for (int nt = 0; nt < 8; ++nt) {
                uint32_t bb[2];
                bb[0] = Vs[kc*8 + t4    ][nt*8 + g];
                bb[1] = Vs[kc*8 + t4 + 4][nt*8 + g];
                mma_tf32(accO[nt], a, bb);
            }
        }
    }

    // write O (fp32)
    float inv0 = 1.0f / l_run[0], inv1 = 1.0f / l_run[1];
    #pragma unroll
    for (int nt = 0; nt < 8; ++nt) {
        int r0 = b * SS + rb + w16 + g;
        int c = h * HDIM + nt*8 + 2*t4;
        *(float2*)(out + (size_t)r0 * DD + c) =
            make_float2(accO[nt][0] * inv0, accO[nt][1] * inv0);
        *(float2*)(out + (size_t)(r0 + 8) * DD + c) =
            make_float2(accO[nt][2] * inv1, accO[nt][3] * inv1);
    }
}

// ---------------- host orchestration ------------------------------------
extern "C" void kernel_launch(void* const* d_in, const int* in_sizes, int n_in,
                              void* d_out, int out_size) {
    const void*  x    = d_in[0];
    const float* tok  = (const float*)d_in[1];
    const float* pos  = (const float*)d_in[2];
    const float* Wq   = (const float*)d_in[3];
    const float* bq   = (const float*)d_in[4];
    const float* Wk   = (const float*)d_in[5];
    const float* bk   = (const float*)d_in[6];
    const float* Wv   = (const float*)d_in[7];
    const float* bv   = (const float*)d_in[8];
    const float* Wo   = (const float*)d_in[9];
    const float* bo   = (const float*)d_in[10];
    const float* ln1g = (const float*)d_in[11];
    const float* ln1b = (const float*)d_in[12];
    const float* ln2g = (const float*)d_in[13];
    const float* ln2b = (const float*)d_in[14];
    const float* W1   = (const float*)d_in[15];
    const float* b1   = (const float*)d_in[16];
    const float* W2   = (const float*)d_in[17];
    const float* b2   = (const float*)d_in[18];
    const float* lnfg = (const float*)d_in[19];
    const float* lnfb = (const float*)d_in[20];
    const float* Wout = (const float*)d_in[21];
    const float* bout = (const float*)d_in[22];

    float *h, *ain, *q, *k, *v, *attn, *mid;
    float *wq, *wk, *wv, *wo, *w1, *w2, *wout;
    cudaGetSymbolAddress((void**)&h,    g_h);
    cudaGetSymbolAddress((void**)&ain,  g_ain);
    cudaGetSymbolAddress((void**)&q,    g_q);
    cudaGetSymbolAddress((void**)&k,    g_k);
    cudaGetSymbolAddress((void**)&v,    g_v);
    cudaGetSymbolAddress((void**)&attn, g_attn);
    cudaGetSymbolAddress((void**)&mid,  g_mid);
    cudaGetSymbolAddress((void**)&wq,   g_wq);
    cudaGetSymbolAddress((void**)&wk,   g_wk);
    cudaGetSymbolAddress((void**)&wv,   g_wv);
    cudaGetSymbolAddress((void**)&wo,   g_wo);
    cudaGetSymbolAddress((void**)&w1,   g_w1);
    cudaGetSymbolAddress((void**)&w2,   g_w2);
    cudaGetSymbolAddress((void**)&wout, g_wout);

    cudaFuncSetAttribute(flash_tc, cudaFuncAttributeMaxDynamicSharedMemorySize,
                         FLASH_SMEM);

    // weight tf32 pre-conversion
    {
        const int nD = LL * DD * DD / 4, nF = LL * DD * FF / 4;
        const int nO = DD * VV / 4;
        w_conv_kernel<<<(nD + 255) / 256, 256>>>((const float4*)Wq, (float4*)wq, nD);
        w_conv_kernel<<<(nD + 255) / 256, 256>>>((const float4*)Wk, (float4*)wk, nD);
        w_conv_kernel<<<(nD + 255) / 256, 256>>>((const float4*)Wv, (float4*)wv, nD);
        w_conv_kernel<<<(nD + 255) / 256, 256>>>((const float4*)Wo, (float4*)wo, nD);
        w_conv_kernel<<<(nF + 255) / 256, 256>>>((const float4*)W1, (float4*)w1, nF);
        w_conv_kernel<<<(nF + 255) / 256, 256>>>((const float4*)W2, (float4*)w2, nF);
        w_conv_kernel<<<(nO + 255) / 256, 256>>>((const float4*)Wout, (float4*)wout, nO);
    }

    embed_kernel<<<MM, 256>>>(x, tok, pos);

    dim3 gDD(DD / 128, MM / 128);
    dim3 gQKV(DD / 128, MM / 128, 3);
    dim3 gFF(FF / 128, MM / 128);
    dim3 gVV(VV / 128, MM / 128);
    dim3 gFL(SS / 64, BB * HH);

    for (int l = 0; l < LL; ++l) {
        const size_t wD = (size_t)l * DD * DD;
        ln_kernel<<<MM, 256>>>(h, ln1g + (size_t)l * DD, ln1b + (size_t)l * DD, ain);
        gemm_qkv<<<gQKV, 256>>>(ain, wq + wD, wk + wD, wv + wD,
                                bq + (size_t)l * DD, bk + (size_t)l * DD,
                                bv + (size_t)l * DD, q, k, v);

        flash_tc<<<gFL, 128, FLASH_SMEM>>>(q, k, v, attn);

        gemm_tf32<<<gDD, 256>>>(attn, wo + wD, bo + (size_t)l * DD, h, h, DD, DD, 0);

        ln_kernel<<<MM, 256>>>(h, ln2g + (size_t)l * DD, ln2b + (size_t)l * DD, ain);
        gemm_tf32<<<gFF, 256>>>(ain, w1 + (size_t)l * DD * FF, b1 + (size_t)l * FF,
                                nullptr, mid, FF, DD, 1);
        gemm_tf32<<<gDD, 256>>>(mid, w2 + (size_t)l * FF * DD, b2 + (size_t)l * DD,
                                h, h, DD, FF, 0);
    }

    ln_kernel<<<MM, 256>>>(h, lnfg, lnfb, ain);
    gemm_tf32<<<gVV, 256>>>(ain, wout, bout, nullptr, (float*)d_out, VV, DD, 0);
}

// round 16
// speedup vs baseline: 1.2012x; 1.2012x over previous
#include <cuda_runtime.h>
#include <cstdint>
#include <cstddef>

#define BB 2
#define SS 1024
#define DD 1024
#define HH 16
#define LL 3
#define FF 4096
#define VV 32000
#define HDIM 64
#define MM (BB*SS)

// ---------------- static scratch ----------------------------------------
__device__ float g_h[BB*SS*DD];
__device__ float g_ain[BB*SS*DD];      // LN out, tf32-rounded
__device__ float g_q[BB*SS*DD];
__device__ float g_k[BB*SS*DD];
__device__ float g_v[BB*SS*DD];
__device__ float g_attn[BB*SS*DD];     // flash out, tf32-rounded
__device__ float g_mid[BB*SS*FF];      // GELU out, tf32-rounded
// tf32-rounded weights (original [K][N] layout)
__device__ float g_wq[LL*DD*DD];
__device__ float g_wk[LL*DD*DD];
__device__ float g_wv[LL*DD*DD];
__device__ float g_wo[LL*DD*DD];
__device__ float g_w1[LL*DD*FF];
__device__ float g_w2[LL*FF*DD];
__device__ float g_wout[(size_t)DD*VV];

// ---------------- helpers -----------------------------------------------
__device__ __forceinline__ uint32_t f2tf(float x) {
    uint32_t r; asm("cvt.rna.tf32.f32 %0, %1;" : "=r"(r) : "f"(x)); return r;
}
__device__ __forceinline__ float tfround(float x) { return __uint_as_float(f2tf(x)); }
__device__ __forceinline__ void mma_tf32(float* c, const uint32_t* a, const uint32_t* b) {
    asm volatile(
        "mma.sync.aligned.m16n8k8.row.col.f32.tf32.tf32.f32 "
        "{%0,%1,%2,%3}, {%4,%5,%6,%7}, {%8,%9}, {%0,%1,%2,%3};"
        : "+f"(c[0]), "+f"(c[1]), "+f"(c[2]), "+f"(c[3])
        : "r"(a[0]), "r"(a[1]), "r"(a[2]), "r"(a[3]), "r"(b[0]), "r"(b[1]));
}
__device__ __forceinline__ void cp16(void* smem, const void* gmem) {
    uint32_t sa = (uint32_t)__cvta_generic_to_shared(smem);
    asm volatile("cp.async.cg.shared.global [%0], [%1], 16;\n" :: "r"(sa), "l"(gmem));
}
__device__ __forceinline__ void cp_commit() {
    asm volatile("cp.async.commit_group;\n" ::: "memory");
}
__device__ __forceinline__ void cp_wait_all() {
    asm volatile("cp.async.wait_group 0;\n" ::: "memory");
}

// ---------------- weight tf32 pre-round ---------------------------------
__global__ void w_conv_kernel(const float4* __restrict__ src,
                              float4* __restrict__ dst, int n4) {
    int i = blockIdx.x * 256 + threadIdx.x;
    if (i < n4) {
        float4 v = src[i];
        v.x = tfround(v.x); v.y = tfround(v.y);
        v.z = tfround(v.z); v.w = tfround(v.w);
        dst[i] = v;
    }
}

// ---------------- embedding ---------------------------------------------
__global__ void embed_kernel(const void* __restrict__ x,
                             const float* __restrict__ tok,
                             const float* __restrict__ pos) {
    int row = blockIdx.x;
    int s = row % SS;
    const int* xi = (const int*)x;
    bool is64 = true;
    #pragma unroll
    for (int t = 0; t < 8; ++t) is64 = is64 && (xi[2*t+1] == 0);
    long long tokid = is64 ? ((const long long*)x)[row] : (long long)xi[row];
    const float* te = tok + (size_t)tokid * DD;
    const float* pe = pos + (size_t)s * DD;
    float* out = g_h + (size_t)row * DD;
    for (int c = threadIdx.x; c < DD; c += blockDim.x)
        out[c] = te[c] + pe[c];
}

// ---------------- layernorm (tf32-rounded output) ------------------------
__global__ void ln_kernel(const float* __restrict__ in,
                          const float* __restrict__ g,
                          const float* __restrict__ b,
                          float* __restrict__ out) {
    int row = blockIdx.x;
    const float* xr = in + (size_t)row * DD;
    float s = 0.f, s2 = 0.f;
    for (int c = threadIdx.x; c < DD; c += 256) {
        float v = xr[c]; s += v; s2 += v * v;
    }
    __shared__ float red[16];
    #pragma unroll
    for (int o = 16; o; o >>= 1) {
        s  += __shfl_down_sync(0xffffffffu, s,  o);
        s2 += __shfl_down_sync(0xffffffffu, s2, o);
    }
    int wid = threadIdx.x >> 5, lid = threadIdx.x & 31;
    if (lid == 0) { red[wid] = s; red[wid + 8] = s2; }
    __syncthreads();
    if (threadIdx.x == 0) {
        float ts = 0.f, ts2 = 0.f;
        #pragma unroll
        for (int w = 0; w < 8; ++w) { ts += red[w]; ts2 += red[w + 8]; }
        red[0] = ts; red[8] = ts2;
    }
    __syncthreads();
    float mu  = red[0] * (1.0f / DD);
    float var = red[8] * (1.0f / DD) - mu * mu;
    float inv = rsqrtf(var + 1e-5f);
    float* outr = out + (size_t)row * DD;
    for (int c = threadIdx.x; c < 256; c += 256) (void)0;
    for (int c = threadIdx.x; c < DD; c += 256)
        outr[c] = tfround((xr[c] - mu) * inv * g[c] + b[c]);
}

// ---------------- tf32 GEMM: 128x128 tile, BK=32, 2-stage cp.async -------
// A[M][K] tf32-rounded (raw bits), B[K][N] tf32-rounded (raw bits).
// A smem [m][36], B smem [k][136] — both fragment-conflict-free.
// flags: bit0 = exact GELU, bit1 = tf32-round output.
#define GSM_A (128*36)
#define GSM_B (32*136)
#define GSM_STAGE (GSM_A + GSM_B)
#define GEMM_SMEM (2*GSM_STAGE*4)

__device__ __forceinline__
void gemm_body(const float* __restrict__ A, const float* __restrict__ Bm,
               const float* __restrict__ bias, const float* __restrict__ res,
               float* __restrict__ C, int N, int K, int flags) {
    extern __shared__ float gsm[];
    int tid = threadIdx.x;
    int lane = tid & 31, warp = tid >> 5;
    int wm = (warp >> 1) * 32;
    int wn = (warp & 1) * 64;
    int g  = lane >> 2, t4 = lane & 3;
    int row0 = blockIdx.y * 128, col0 = blockIdx.x * 128;

    float acc[2][8][4] = {};

    // staging: 4 float4 of A + 4 float4 of B per thread per stage
    #define STAGE(buf, kk) do {                                               \
        float* As_ = gsm + (buf) * GSM_STAGE;                                 \
        float* Bs_ = As_ + GSM_A;                                             \
        _Pragma("unroll")                                                     \
        for (int i_ = 0; i_ < 4; ++i_) {                                      \
            int f_ = tid + i_ * 256;                                          \
            int ar_ = f_ >> 3, ak_ = (f_ & 7) * 4;                            \
            cp16(As_ + ar_ * 36 + ak_,                                        \
                 A + (size_t)(row0 + ar_) * K + (kk) + ak_);                  \
            int bk_ = f_ >> 5, bn_ = (f_ & 31) * 4;                           \
            cp16(Bs_ + bk_ * 136 + bn_,                                       \
                 Bm + (size_t)((kk) + bk_) * N + col0 + bn_);                 \
        }                                                                     \
        cp_commit();                                                          \
    } while (0)

    STAGE(0, 0);
    cp_wait_all();
    __syncthreads();

    int cur = 0;
    for (int kk = 0; kk < K; kk += 32) {
        bool has_next = (kk + 32) < K;
        if (has_next) STAGE(cur ^ 1, kk + 32);

        const float* Ab = gsm + cur * GSM_STAGE;
        const float* Bb = Ab + GSM_A;
        #pragma unroll
        for (int ks = 0; ks < 4; ++ks) {
            uint32_t af[2][4];
            #pragma unroll
            for (int mi = 0; mi < 2; ++mi) {
                int m = wm + mi * 16 + g;
                af[mi][0] = __float_as_uint(Ab[(m    ) * 36 + ks*8 + t4    ]);
                af[mi][1] = __float_as_uint(Ab[(m + 8) * 36 + ks*8 + t4    ]);
                af[mi][2] = __float_as_uint(Ab[(m    ) * 36 + ks*8 + t4 + 4]);
                af[mi][3] = __float_as_uint(Ab[(m + 8) * 36 + ks*8 + t4 + 4]);
            }
            #pragma unroll
            for (int ni = 0; ni < 8; ++ni) {
                int n = wn + ni * 8 + g;
                uint32_t bf[2];
                bf[0] = __float_as_uint(Bb[(ks*8 + t4    ) * 136 + n]);
                bf[1] = __float_as_uint(Bb[(ks*8 + t4 + 4) * 136 + n]);
                mma_tf32(acc[0][ni], af[0], bf);
                mma_tf32(acc[1][ni], af[1], bf);
            }
        }
        if (has_next) {
            cp_wait_all();
            __syncthreads();
            cur ^= 1;
        }
    }
    #undef STAGE

    // epilogue
    #pragma unroll
    for (int mi = 0; mi < 2; ++mi) {
        #pragma unroll
        for (int ni = 0; ni < 8; ++ni) {
            int r = row0 + wm + mi * 16 + g;
            int c = col0 + wn + ni * 8 + 2 * t4;
            float bc0 = bias[c], bc1 = bias[c + 1];
            #pragma unroll
            for (int half = 0; half < 2; ++half) {
                int rr = r + half * 8;
                float v0 = acc[mi][ni][half * 2 + 0] + bc0;
                float v1 = acc[mi][ni][half * 2 + 1] + bc1;
                if (flags & 1) {
                    v0 = 0.5f * v0 * (1.0f + erff(v0 * 0.70710678118654752f));
                    v1 = 0.5f * v1 * (1.0f + erff(v1 * 0.70710678118654752f));
                }
                if (res) {
                    v0 += res[(size_t)rr * N + c];
                    v1 += res[(size_t)rr * N + c + 1];
                }
                if (flags & 2) { v0 = tfround(v0); v1 = tfround(v1); }
                *(float2*)(C + (size_t)rr * N + c) = make_float2(v0, v1);
            }
        }
    }
}

__global__ __launch_bounds__(256, 2)
void gemm_tf32(const float* __restrict__ A, const float* __restrict__ Bm,
               const float* __restrict__ bias, const float* __restrict__ res,
               float* __restrict__ C, int N, int K, int flags) {
    gemm_body(A, Bm, bias, res, C, N, K, flags);
}

__global__ __launch_bounds__(256, 2)
void gemm_qkv(const float* __restrict__ A,
              const float* __restrict__ W0, const float* __restrict__ W1_,
              const float* __restrict__ W2_,
              const float* __restrict__ b0, const float* __restrict__ b1_,
              const float* __restrict__ b2_,
              float* __restrict__ C0, float* __restrict__ C1,
              float* __restrict__ C2) {
    const float* Bm; const float* bias; float* C;
    if (blockIdx.z == 0)      { Bm = W0;  bias = b0;  C = C0; }
    else if (blockIdx.z == 1) { Bm = W1_; bias = b1_; C = C1; }
    else                      { Bm = W2_; bias = b2_; C = C2; }
    gemm_body(A, Bm, bias, nullptr, C, DD, DD, 0);
}

// ---------------- tf32 flash attention (output tf32-rounded) -------------
#define QS_OFF 0
#define KS_OFF (64*68)
#define VS_OFF (KS_OFF + 64*68)
#define PS_OFF (VS_OFF + 64*72)
#define FLASH_SMEM ((PS_OFF + 64*72) * 4)

__global__ __launch_bounds__(128)
void flash_tc(const float* __restrict__ q, const float* __restrict__ kmat,
              const float* __restrict__ v, float* __restrict__ out) {
    extern __shared__ uint32_t fsm[];
    uint32_t (*Qs)[68] = (uint32_t(*)[68])(fsm + QS_OFF);
    uint32_t (*Ks)[68] = (uint32_t(*)[68])(fsm + KS_OFF);
    uint32_t (*Vs)[72] = (uint32_t(*)[72])(fsm + VS_OFF);
    uint32_t (*Ps)[72] = (uint32_t(*)[72])(fsm + PS_OFF);

    int bh = blockIdx.y;
    int b = bh >> 4, h = bh & 15;
    int rb = blockIdx.x * 64;
    const float* Q  = q    + (size_t)b * SS * DD + h * HDIM;
    const float* Kp = kmat + (size_t)b * SS * DD + h * HDIM;
    const float* V  = v    + (size_t)b * SS * DD + h * HDIM;

    int tid = threadIdx.x;
    int lane = tid & 31, warp = tid >> 5;
    int g = lane >> 2, t4 = lane & 3;
    int w16 = warp * 16;

    #pragma unroll
    for (int it = 0; it < 8; ++it) {
        int idx = it * 128 + tid;
        int row = idx >> 4, d4 = (idx & 15) * 4;
        float4 qv = *(const float4*)(Q + (size_t)(rb + row) * DD + d4);
        Qs[row][d4+0] = f2tf(qv.x); Qs[row][d4+1] = f2tf(qv.y);
        Qs[row][d4+2] = f2tf(qv.z); Qs[row][d4+3] = f2tf(qv.w);
    }

    float m_run[2] = {-1e30f, -1e30f};
    float l_run[2] = {0.f, 0.f};
    float accO[8][4] = {};

    int nblk = rb / 64 + 1;
    for (int blk = 0; blk < nblk; ++blk) {
        int j0 = blk * 64;
        __syncthreads();
        #pragma unroll
        for (int it = 0; it < 8; ++it) {
            int idx = it * 128 + tid;
            int row = idx >> 4, d4 = (idx & 15) * 4;
            float4 kv = *(const float4*)(Kp + (size_t)(j0 + row) * DD + d4);
            Ks[row][d4+0] = f2tf(kv.x); Ks[row][d4+1] = f2tf(kv.y);
            Ks[row][d4+2] = f2tf(kv.z); Ks[row][d4+3] = f2tf(kv.w);
            float4 vv = *(const float4*)(V + (size_t)(j0 + row) * DD + d4);
            Vs[row][d4+0] = f2tf(vv.x); Vs[row][d4+1] = f2tf(vv.y);
            Vs[row][d4+2] = f2tf(vv.z); Vs[row][d4+3] = f2tf(vv.w);
        }
        __syncthreads();

        float sacc[8][4] = {};
        #pragma unroll
        for (int kc = 0; kc < 8; ++kc) {
            uint32_t a[4];
            a[0] = Qs[w16 + g    ][kc*8 + t4    ];
            a[1] = Qs[w16 + g + 8][kc*8 + t4    ];
            a[2] = Qs[w16 + g    ][kc*8 + t4 + 4];
            a[3] = Qs[w16 + g + 8][kc*8 + t4 + 4];
            #pragma unroll
            for (int nt = 0; nt < 8; ++nt) {
                uint32_t bb[2];
                bb[0] = Ks[nt*8 + g][kc*8 + t4    ];
                bb[1] = Ks[nt*8 + g][kc*8 + t4 + 4];
                mma_tf32(sacc[nt], a, bb);
            }
        }

        #pragma unroll
        for (int hf = 0; hf < 2; ++hf) {
            int row = rb + w16 + g + hf * 8;
            float sv[8][2];
            float mloc = -1e30f;
            #pragma unroll
            for (int nt = 0; nt < 8; ++nt) {
                #pragma unroll
                for (int jj = 0; jj < 2; ++jj) {
                    float s = sacc[nt][hf*2 + jj] * 0.125f;
                    int col = j0 + nt*8 + 2*t4 + jj;
                    if (col > row) s = -1e30f;
                    sv[nt][jj] = s;
                    mloc = fmaxf(mloc, s);
                }
            }
            mloc = fmaxf(mloc, __shfl_xor_sync(0xffffffffu, mloc, 1));
            mloc = fmaxf(mloc, __shfl_xor_sync(0xffffffffu, mloc, 2));
            float mnew = fmaxf(m_run[hf], mloc);
            float sc = __expf(m_run[hf] - mnew);
            float ls = 0.f;
            #pragma unroll
            for (int nt = 0; nt < 8; ++nt) {
                #pragma unroll
                for (int jj = 0; jj < 2; ++jj) {
                    float p = __expf(sv[nt][jj] - mnew);
                    ls += p;
                    Ps[nt*8 + 2*t4 + jj][w16 + g + hf*8] = f2tf(p);
                }
            }
            ls += __shfl_xor_sync(0xffffffffu, ls, 1);
            ls += __shfl_xor_sync(0xffffffffu, ls, 2);
            l_run[hf] = l_run[hf] * sc + ls;
            m_run[hf] = mnew;
            #pragma unroll
            for (int nt = 0; nt < 8; ++nt) {
                accO[nt][hf*2 + 0] *= sc;
                accO[nt][hf*2 + 1] *= sc;
            }
        }
        __syncwarp();

        #pragma unroll
        for (int kc = 0; kc < 8; ++kc) {
            uint32_t a[4];
            a[0] = Ps[kc*8 + t4    ][w16 + g    ];
            a[1] = Ps[kc*8 + t4    ][w16 + g + 8];
            a[2] = Ps[kc*8 + t4 + 4][w16 + g    ];
            a[3] = Ps[kc*8 + t4 + 4][w16 + g + 8];
            #pragma unroll
            for (int nt = 0; nt < 8; ++nt) {
                uint32_t bb[2];
                bb[0] = Vs[kc*8 + t4    ][nt*8 + g];
                bb[1] = Vs[kc*8 + t4 + 4][nt*8 + g];
                mma_tf32(accO[nt], a, bb);
            }
        }
    }

    float inv0 = 1.0f / l_run[0], inv1 = 1.0f / l_run[1];
    #pragma unroll
    for (int nt = 0; nt < 8; ++nt) {
        int r0 = b * SS + rb + w16 + g;
        int c = h * HDIM + nt*8 + 2*t4;
        *(float2*)(out + (size_t)r0 * DD + c) =
            make_float2(tfround(accO[nt][0] * inv0), tfround(accO[nt][1] * inv0));
        *(float2*)(out + (size_t)(r0 + 8) * DD + c) =
            make_float2(tfround(accO[nt][2] * inv1), tfround(accO[nt][3] * inv1));
    }
}

// ---------------- host orchestration ------------------------------------
extern "C" void kernel_launch(void* const* d_in, const int* in_sizes, int n_in,
                              void* d_out, int out_size) {
    const void*  x    = d_in[0];
    const float* tok  = (const float*)d_in[1];
    const float* pos  = (const float*)d_in[2];
    const float* Wq   = (const float*)d_in[3];
    const float* bq   = (const float*)d_in[4];
    const float* Wk   = (const float*)d_in[5];
    const float* bk   = (const float*)d_in[6];
    const float* Wv   = (const float*)d_in[7];
    const float* bv   = (const float*)d_in[8];
    const float* Wo   = (const float*)d_in[9];
    const float* bo   = (const float*)d_in[10];
    const float* ln1g = (const float*)d_in[11];
    const float* ln1b = (const float*)d_in[12];
    const float* ln2g = (const float*)d_in[13];
    const float* ln2b = (const float*)d_in[14];
    const float* W1   = (const float*)d_in[15];
    const float* b1   = (const float*)d_in[16];
    const float* W2   = (const float*)d_in[17];
    const float* b2   = (const float*)d_in[18];
    const float* lnfg = (const float*)d_in[19];
    const float* lnfb = (const float*)d_in[20];
    const float* Wout = (const float*)d_in[21];
    const float* bout = (const float*)d_in[22];

    float *h, *ain, *q, *k, *v, *attn, *mid;
    float *wq, *wk, *wv, *wo, *w1, *w2, *wout;
    cudaGetSymbolAddress((void**)&h,    g_h);
    cudaGetSymbolAddress((void**)&ain,  g_ain);
    cudaGetSymbolAddress((void**)&q,    g_q);
    cudaGetSymbolAddress((void**)&k,    g_k);
    cudaGetSymbolAddress((void**)&v,    g_v);
    cudaGetSymbolAddress((void**)&attn, g_attn);
    cudaGetSymbolAddress((void**)&mid,  g_mid);
    cudaGetSymbolAddress((void**)&wq,   g_wq);
    cudaGetSymbolAddress((void**)&wk,   g_wk);
    cudaGetSymbolAddress((void**)&wv,   g_wv);
    cudaGetSymbolAddress((void**)&wo,   g_wo);
    cudaGetSymbolAddress((void**)&w1,   g_w1);
    cudaGetSymbolAddress((void**)&w2,   g_w2);
    cudaGetSymbolAddress((void**)&wout, g_wout);

    cudaFuncSetAttribute(flash_tc, cudaFuncAttributeMaxDynamicSharedMemorySize,
                         FLASH_SMEM);
    cudaFuncSetAttribute(gemm_tf32, cudaFuncAttributeMaxDynamicSharedMemorySize,
                         GEMM_SMEM);
    cudaFuncSetAttribute(gemm_qkv, cudaFuncAttributeMaxDynamicSharedMemorySize,
                         GEMM_SMEM);

    // weight tf32 pre-round
    {
        const int nD = LL * DD * DD / 4, nF = LL * DD * FF / 4;
        const int nO = DD * VV / 4;
        w_conv_kernel<<<(nD + 255) / 256, 256>>>((const float4*)Wq, (float4*)wq, nD);
        w_conv_kernel<<<(nD + 255) / 256, 256>>>((const float4*)Wk, (float4*)wk, nD);
        w_conv_kernel<<<(nD + 255) / 256, 256>>>((const float4*)Wv, (float4*)wv, nD);
        w_conv_kernel<<<(nD + 255) / 256, 256>>>((const float4*)Wo, (float4*)wo, nD);
        w_conv_kernel<<<(nF + 255) / 256, 256>>>((const float4*)W1, (float4*)w1, nF);
        w_conv_kernel<<<(nF + 255) / 256, 256>>>((const float4*)W2, (float4*)w2, nF);
        w_conv_kernel<<<(nO + 255) / 256, 256>>>((const float4*)Wout, (float4*)wout, nO);
    }

    embed_kernel<<<MM, 256>>>(x, tok, pos);

    dim3 gDD(DD / 128, MM / 128);
    dim3 gQKV(DD / 128, MM / 128, 3);
    dim3 gFF(FF / 128, MM / 128);
    dim3 gVV(VV / 128, MM / 128);
    dim3 gFL(SS / 64, BB * HH);

    for (int l = 0; l < LL; ++l) {
        const size_t wD = (size_t)l * DD * DD;
        ln_kernel<<<MM, 256>>>(h, ln1g + (size_t)l*DD, ln1b + (size_t)l*DD, ain);
        gemm_qkv<<<gQKV, 256, GEMM_SMEM>>>(ain, wq + wD, wk + wD, wv + wD,
                                bq + (size_t)l*DD, bk + (size_t)l*DD,
                                bv + (size_t)l*DD, q, k, v);

        flash_tc<<<gFL, 128, FLASH_SMEM>>>(q, k, v, attn);

        gemm_tf32<<<gDD, 256, GEMM_SMEM>>>(attn, wo + wD, bo + (size_t)l*DD,
                                           h, h, DD, DD, 0);

        ln_kernel<<<MM, 256>>>(h, ln2g + (size_t)l*DD, ln2b + (size_t)l*DD, ain);
        gemm_tf32<<<gFF, 256, GEMM_SMEM>>>(ain, w1 + (size_t)l*DD*FF,
                                           b1 + (size_t)l*FF, nullptr, mid,
                                           FF, DD, 3);
        gemm_tf32<<<gDD, 256, GEMM_SMEM>>>(mid, w2 + (size_t)l*FF*DD,
                                           b2 + (size_t)l*DD, h, h, DD, FF, 0);
    }

    ln_kernel<<<MM, 256>>>(h, lnfg, lnfb, ain);
    gemm_tf32<<<gVV, 256, GEMM_SMEM>>>(ain, wout, bout, nullptr, (float*)d_out,
                                       VV, DD, 0);
}